// round 5
// baseline (speedup 1.0000x reference)
#include <cuda_runtime.h>

#define N_NODES    50000
#define N_EDGES    800000
#define NUM_GRAPHS 256
#define IN_DIM     128
#define HDIM       64
#define HID        256
#define BN_EPS     1e-5f

// ---------------- scratch (device globals; 16B-aligned for float4 access) ----------------
__device__ __align__(16) float g_yl  [N_NODES * HDIM];
__device__ __align__(16) float g_yr  [N_NODES * HDIM];
__device__ __align__(16) float g_h1  [N_NODES * HDIM];
__device__ __align__(16) float g_h2  [N_NODES * HDIM];
__device__ __align__(16) float g_pool[NUM_GRAPHS * HDIM];
__device__ __align__(16) float g_t1  [NUM_GRAPHS * HID];
__device__ __align__(16) float g_t2  [NUM_GRAPHS * (HID/2)];
__device__ __align__(16) float g_t3  [NUM_GRAPHS * (HID/4)];
__device__ __align__(16) int   g_deg     [N_NODES];
__device__ __align__(16) int   g_rowstart[N_NODES + 1];
__device__ __align__(16) int   g_cursor  [N_NODES];
__device__ __align__(16) int   g_csr     [N_EDGES];
__device__ __align__(16) int   g_gstart  [NUM_GRAPHS + 1];
__device__ int g_idx64;   // 1 if index tensors are int64, 0 if int32

// dtype-flexible index load (hot path never uses this; CSR is int32)
__device__ __forceinline__ int load_idx(const void* p, long i) {
    return g_idx64 ? (int)((const long long*)p)[i] : ((const int*)p)[i];
}
__device__ __forceinline__ int clampi(int v, int lo, int hi) {
    return v < lo ? lo : (v > hi ? hi : v);
}

// buffer selectors (device-side; no host symbol lookup needed)
__device__ __forceinline__ const float* node_buf(int sel, const float* xparam) {
    return sel == 0 ? xparam : (sel == 1 ? g_h1 : g_h2);   // 0=x, 1=h1, 2=h2
}
__device__ __forceinline__ float* hdst_buf(int sel) {
    return sel == 1 ? g_h1 : g_h2;
}
__device__ __forceinline__ const float* mlp_src(int sel) {
    switch (sel) { case 0: return g_pool; case 1: return g_t1;
                   case 2: return g_t2;  default: return g_t3; }
}
__device__ __forceinline__ float* mlp_dst(int sel, float* outparam) {
    switch (sel) { case 1: return g_t1; case 2: return g_t2;
                   case 3: return g_t3; default: return outparam; }
}

// ---------------- dtype detection: int64 layout => odd 32-bit words all zero ----------------
// Samples 128 pairs from the src row and 128 from the dst row region.
// (node ids < 50000 << 2^31, so int64 high words are always 0; for an int32
//  buffer those words are random node ids — all-zero is impossible in practice.)
__global__ void k_detect(const int* __restrict__ ei32) {
    if (threadIdx.x == 0) {
        int all0 = 1;
        for (int k = 0; k < 128; k++) {
            if (ei32[2 * k + 1] != 0) { all0 = 0; break; }
            // probe a second region well inside the buffer under BOTH interpretations:
            // int32 buffer has 1.6M ints; indices 2*(100000+k)+1 < 0.3M are safe.
            if (ei32[2 * (100000 + k) + 1] != 0) { all0 = 0; break; }
        }
        g_idx64 = all0;
    }
}

// ---------------- zero in-degree counters ----------------
__global__ void k_zero() {
    int i = blockIdx.x * blockDim.x + threadIdx.x;
    if (i < N_NODES) g_deg[i] = 0;
}

// ---------------- per-dst in-degree ----------------
__global__ void k_count(const void* __restrict__ ei) {
    int e = blockIdx.x * blockDim.x + threadIdx.x;
    if (e >= N_EDGES) return;
    int d = clampi(load_idx(ei, (long)N_EDGES + e), 0, N_NODES - 1);
    atomicAdd(&g_deg[d], 1);
}

// ---------------- single-block prefix sum over degrees -> rowstart, cursor ----------------
__global__ __launch_bounds__(1024) void k_scan() {
    __shared__ int s[1024];
    const int t = threadIdx.x;
    const int C = (N_NODES + 1023) / 1024;   // 49
    const int base = t * C;
    int sum = 0;
    for (int i = 0; i < C; i++) {
        int idx = base + i;
        if (idx < N_NODES) sum += g_deg[idx];
    }
    s[t] = sum; __syncthreads();
    for (int off = 1; off < 1024; off <<= 1) {
        int v = (t >= off) ? s[t - off] : 0;
        __syncthreads();
        s[t] += v;
        __syncthreads();
    }
    int run = (t == 0) ? 0 : s[t - 1];
    for (int i = 0; i < C; i++) {
        int idx = base + i;
        if (idx < N_NODES) {
            g_rowstart[idx] = run;
            g_cursor[idx]   = run;
            run += g_deg[idx];
        }
    }
    if (t == 1023) g_rowstart[N_NODES] = run;
}

// ---------------- fill CSR src lists ----------------
__global__ void k_fill(const void* __restrict__ ei) {
    int e = blockIdx.x * blockDim.x + threadIdx.x;
    if (e >= N_EDGES) return;
    int s = clampi(load_idx(ei, e),                 0, N_NODES - 1);
    int d = clampi(load_idx(ei, (long)N_EDGES + e), 0, N_NODES - 1);
    int slot = atomicAdd(&g_cursor[d], 1);
    if (slot < N_EDGES) g_csr[slot] = s;
}

// ---------------- graph boundaries via binary search on sorted batch ----------------
__global__ void k_gbounds(const void* __restrict__ batch) {
    int g = blockIdx.x * blockDim.x + threadIdx.x;
    if (g > NUM_GRAPHS) return;
    if (g == NUM_GRAPHS) { g_gstart[g] = N_NODES; return; }
    int lo = 0, hi = N_NODES;
    while (lo < hi) {
        int mid = (lo + hi) >> 1;
        if (load_idx(batch, mid) < g) lo = mid + 1; else hi = mid;
    }
    g_gstart[g] = lo;
}

// ---------------- dual GEMM: g_yl = X@Wl, g_yr = X@Wr  (X:[N,K], W:[K,64]) ----------------
template<int K>
__global__ __launch_bounds__(128) void k_gemm_dual(
    const float* __restrict__ Xparam, int xsel,
    const float* __restrict__ Wl, const float* __restrict__ Wr)
{
    const float* __restrict__ X = node_buf(xsel, Xparam);

    __shared__ float Xs[32][65];
    __shared__ float Wls[64][64];
    __shared__ float Wrs[64][64];

    const int tid  = threadIdx.x;
    const int row0 = blockIdx.x * 32;
    const int rowg = tid >> 4;   // 0..7  (4 rows each)
    const int colg = tid & 15;   // 0..15 (4 cols each)

    float accl[4][4] = {{0.f}}, accr[4][4] = {{0.f}};

    #pragma unroll
    for (int c = 0; c < K / 64; c++) {
        #pragma unroll
        for (int i = 0; i < 4; i++) {
            int f  = tid + i * 128;
            int r  = f >> 4;
            int c4 = f & 15;
            float4 v = make_float4(0.f, 0.f, 0.f, 0.f);
            if (row0 + r < N_NODES)
                v = *(const float4*)(X + (size_t)(row0 + r) * K + c * 64 + c4 * 4);
            Xs[r][c4*4+0] = v.x; Xs[r][c4*4+1] = v.y;
            Xs[r][c4*4+2] = v.z; Xs[r][c4*4+3] = v.w;
        }
        #pragma unroll
        for (int i = 0; i < 8; i++) {
            int f  = tid + i * 128;
            int r  = f >> 4;
            int c4 = f & 15;
            ((float4*)Wls)[r*16 + c4] = *(const float4*)(Wl + (size_t)(c*64 + r) * 64 + c4 * 4);
            ((float4*)Wrs)[r*16 + c4] = *(const float4*)(Wr + (size_t)(c*64 + r) * 64 + c4 * 4);
        }
        __syncthreads();

        #pragma unroll 8
        for (int k = 0; k < 64; k++) {
            float4 wl = ((float4*)Wls)[k*16 + colg];
            float4 wr = ((float4*)Wrs)[k*16 + colg];
            #pragma unroll
            for (int i = 0; i < 4; i++) {
                float xv = Xs[rowg*4 + i][k];
                accl[i][0] += xv * wl.x; accl[i][1] += xv * wl.y;
                accl[i][2] += xv * wl.z; accl[i][3] += xv * wl.w;
                accr[i][0] += xv * wr.x; accr[i][1] += xv * wr.y;
                accr[i][2] += xv * wr.z; accr[i][3] += xv * wr.w;
            }
        }
        __syncthreads();
    }

    #pragma unroll
    for (int i = 0; i < 4; i++) {
        int r = row0 + rowg*4 + i;
        if (r < N_NODES) {
            *(float4*)(g_yl + (size_t)r * 64 + colg * 4) =
                make_float4(accl[i][0], accl[i][1], accl[i][2], accl[i][3]);
            *(float4*)(g_yr + (size_t)r * 64 + colg * 4) =
                make_float4(accr[i][0], accr[i][1], accr[i][2], accr[i][3]);
        }
    }
}

// ---------------- gather-aggregate + finish, fused ----------------
// h[v] = (sum_{u in N(v)} yl[u]) / max(deg,1) + bl + yr[v]
// 16 threads per node, each owning 4 columns (one float4).
__global__ void k_aggregate(const float* __restrict__ bl, int dstsel) {
    int tid = blockIdx.x * blockDim.x + threadIdx.x;
    if (tid >= N_NODES * 16) return;
    float* __restrict__ hout = hdst_buf(dstsel);
    const int v  = tid >> 4;
    const int c4 = (tid & 15) << 2;

    const int start = g_rowstart[v];
    const int end   = g_rowstart[v + 1];

    float4 acc = make_float4(0.f, 0.f, 0.f, 0.f);
    int i = start;
    for (; i + 4 <= end; i += 4) {
        int s0 = g_csr[i], s1 = g_csr[i+1], s2 = g_csr[i+2], s3 = g_csr[i+3];
        float4 a0 = *(const float4*)(g_yl + (size_t)s0 * 64 + c4);
        float4 a1 = *(const float4*)(g_yl + (size_t)s1 * 64 + c4);
        float4 a2 = *(const float4*)(g_yl + (size_t)s2 * 64 + c4);
        float4 a3 = *(const float4*)(g_yl + (size_t)s3 * 64 + c4);
        acc.x += a0.x + a1.x + a2.x + a3.x;
        acc.y += a0.y + a1.y + a2.y + a3.y;
        acc.z += a0.z + a1.z + a2.z + a3.z;
        acc.w += a0.w + a1.w + a2.w + a3.w;
    }
    for (; i < end; i++) {
        int s = g_csr[i];
        float4 a = *(const float4*)(g_yl + (size_t)s * 64 + c4);
        acc.x += a.x; acc.y += a.y; acc.z += a.z; acc.w += a.w;
    }

    float inv = 1.0f / fmaxf((float)(end - start), 1.0f);
    float4 r = *(const float4*)(g_yr + (size_t)v * 64 + c4);
    float4 b = *(const float4*)(bl + c4);
    float4 o = make_float4(acc.x * inv + b.x + r.x,
                           acc.y * inv + b.y + r.y,
                           acc.z * inv + b.z + r.z,
                           acc.w * inv + b.w + r.w);
    *(float4*)(hout + (size_t)v * 64 + c4) = o;
}

// ---------------- contiguous-segment pool (sums; mean folded into lin1) ----------------
__global__ __launch_bounds__(256) void k_pool(int srcsel) {
    const float* __restrict__ h = hdst_buf(srcsel);
    const int g = blockIdx.x;
    const int start = g_gstart[g], end = g_gstart[g + 1];
    const int col = threadIdx.x & 63;
    const int rg  = threadIdx.x >> 6;   // 0..3
    float acc = 0.f;
    for (int v = start + rg; v < end; v += 4)
        acc += h[(size_t)v * 64 + col];
    __shared__ float s[4][64];
    s[rg][col] = acc; __syncthreads();
    if (rg == 0)
        g_pool[(size_t)g * 64 + col] = s[0][col] + s[1][col] + s[2][col] + s[3][col];
}

// ---------------- small MLP GEMM: C[m] = (A[m] * scale) @ W + bias ----------------
__global__ void k_mlp_gemm(int asel, const float* __restrict__ W,
                           const float* __restrict__ bias, int csel,
                           float* outparam, int K, int Nc, int divide) {
    __shared__ float As[256];
    const float* __restrict__ A = mlp_src(asel);
    float* __restrict__ C = mlp_dst(csel, outparam);
    int m = blockIdx.x;
    float scale = 1.0f;
    if (divide) scale = 1.0f / fmaxf((float)(g_gstart[m + 1] - g_gstart[m]), 1.0f);
    for (int k = threadIdx.x; k < K; k += blockDim.x)
        As[k] = A[(size_t)m * K + k] * scale;
    __syncthreads();
    for (int n = threadIdx.x; n < Nc; n += blockDim.x) {
        float acc = bias[n];
        for (int k = 0; k < K; k++)
            acc += As[k] * W[(size_t)k * Nc + n];
        C[(size_t)m * Nc + n] = acc;
    }
}

// ---------------- batchnorm (training stats over 256 rows) + tanh, in place ----------------
__global__ void k_bn_tanh(int sel, const float* __restrict__ gm,
                          const float* __restrict__ bt, int Nc) {
    float* __restrict__ X = mlp_dst(sel, nullptr);
    int col = blockIdx.x;
    int t   = threadIdx.x;      // 256 threads = 256 rows
    __shared__ float red[256];
    float v = X[(size_t)t * Nc + col];
    red[t] = v; __syncthreads();
    for (int s = 128; s > 0; s >>= 1) { if (t < s) red[t] += red[t + s]; __syncthreads(); }
    float mean = red[0] * (1.0f / NUM_GRAPHS);
    __syncthreads();
    float d = v - mean;
    red[t] = d * d; __syncthreads();
    for (int s = 128; s > 0; s >>= 1) { if (t < s) red[t] += red[t + s]; __syncthreads(); }
    float var = red[0] * (1.0f / NUM_GRAPHS);
    X[(size_t)t * Nc + col] = tanhf(d * rsqrtf(var + BN_EPS) * gm[col] + bt[col]);
}

extern "C" void kernel_launch(void* const* d_in, const int* in_sizes, int n_in,
                              void* d_out, int out_size) {
    const float* x     = (const float*)d_in[0];
    const void*  ei    = d_in[1];
    const void*  batch = d_in[2];
    const float* W1l = (const float*)d_in[3];
    const float* b1l = (const float*)d_in[4];
    const float* W1r = (const float*)d_in[5];
    const float* W2l = (const float*)d_in[6];
    const float* b2l = (const float*)d_in[7];
    const float* W2r = (const float*)d_in[8];
    const float* W3l = (const float*)d_in[9];
    const float* b3l = (const float*)d_in[10];
    const float* W3r = (const float*)d_in[11];
    const float* lin1_w = (const float*)d_in[12];
    const float* lin1_b = (const float*)d_in[13];
    const float* g1  = (const float*)d_in[14];
    const float* be1 = (const float*)d_in[15];
    const float* lin2_w = (const float*)d_in[16];
    const float* lin2_b = (const float*)d_in[17];
    const float* g2  = (const float*)d_in[18];
    const float* be2 = (const float*)d_in[19];
    const float* lin3_w = (const float*)d_in[20];
    const float* lin3_b = (const float*)d_in[21];
    const float* g3  = (const float*)d_in[22];
    const float* be3 = (const float*)d_in[23];
    const float* lin4_w = (const float*)d_in[24];
    const float* lin4_b = (const float*)d_in[25];
    float* out = (float*)d_out;

    const int T = 256;
    const int gemm_grid   = (N_NODES + 31) / 32;
    const int edge_grid   = (N_EDGES + T - 1) / T;
    const int node16_grid = (N_NODES * 16 + T - 1) / T;

    // ---- detect index dtype, build CSR + graph bounds (shared across layers)
    k_detect <<<1, 32>>>((const int*)ei);
    k_zero   <<<(N_NODES + T - 1) / T, T>>>();
    k_count  <<<edge_grid, T>>>(ei);
    k_scan   <<<1, 1024>>>();
    k_fill   <<<edge_grid, T>>>(ei);
    k_gbounds<<<2, 256>>>(batch);

    // --- SAGE layer 1: x [N,128] -> h1 [N,64]
    k_gemm_dual<IN_DIM><<<gemm_grid, 128>>>(x, 0, W1l, W1r);
    k_aggregate<<<node16_grid, T>>>(b1l, 1);

    // --- SAGE layer 2: h1 -> h2
    k_gemm_dual<HDIM><<<gemm_grid, 128>>>(nullptr, 1, W2l, W2r);
    k_aggregate<<<node16_grid, T>>>(b2l, 2);

    // --- SAGE layer 3: h2 -> h1
    k_gemm_dual<HDIM><<<gemm_grid, 128>>>(nullptr, 2, W3l, W3r);
    k_aggregate<<<node16_grid, T>>>(b3l, 1);

    // --- global mean pool (sums; mean folded into lin1)
    k_pool<<<NUM_GRAPHS, 256>>>(1);

    // --- MLP head
    k_mlp_gemm<<<NUM_GRAPHS, 256>>>(0, lin1_w, lin1_b, 1, nullptr, HDIM,  HID,   1);
    k_bn_tanh <<<HID,        256>>>(1, g1, be1, HID);
    k_mlp_gemm<<<NUM_GRAPHS, 256>>>(1, lin2_w, lin2_b, 2, nullptr, HID,   HID/2, 0);
    k_bn_tanh <<<HID/2,      256>>>(2, g2, be2, HID/2);
    k_mlp_gemm<<<NUM_GRAPHS, 256>>>(2, lin3_w, lin3_b, 3, nullptr, HID/2, HID/4, 0);
    k_bn_tanh <<<HID/4,      256>>>(3, g3, be3, HID/4);
    k_mlp_gemm<<<NUM_GRAPHS, 256>>>(3, lin4_w, lin4_b, 0, out,     HID/4, 10,    0);
}

// round 6
// speedup vs baseline: 1.4296x; 1.4296x over previous
#include <cuda_runtime.h>

#define N_NODES    50000
#define N_EDGES    800000
#define NUM_GRAPHS 256
#define IN_DIM     128
#define HDIM       64
#define HID        256
#define BN_EPS     1e-5f

#define SCAN_BLOCKS ((N_NODES + 255) / 256)   // 196

// ---------------- scratch (device globals; 16B-aligned for float4 access) ----------------
__device__ __align__(16) float g_yl  [N_NODES * HDIM];
__device__ __align__(16) float g_yr  [N_NODES * HDIM];
__device__ __align__(16) float g_h1  [N_NODES * HDIM];
__device__ __align__(16) float g_h2  [N_NODES * HDIM];
__device__ __align__(16) float g_pool[NUM_GRAPHS * HDIM];
__device__ __align__(16) float g_t1  [NUM_GRAPHS * HID];
__device__ __align__(16) float g_t2  [NUM_GRAPHS * (HID/2)];
__device__ __align__(16) float g_t3  [NUM_GRAPHS * (HID/4)];
__device__ __align__(16) int   g_deg     [N_NODES];
__device__ __align__(16) int   g_rowstart[N_NODES + 1];
__device__ __align__(16) int   g_cursor  [N_NODES];
__device__ __align__(16) int   g_csr     [N_EDGES];
__device__ __align__(16) int   g_gstart  [NUM_GRAPHS + 1];
__device__ __align__(16) int   g_bsum    [SCAN_BLOCKS];
__device__ __align__(16) int   g_boff    [SCAN_BLOCKS];
__device__ int g_idx64;   // 1 if index tensors are int64, 0 if int32

// dtype-flexible index load (hot path never uses this; CSR is int32)
__device__ __forceinline__ int load_idx(const void* p, long i) {
    return g_idx64 ? (int)((const long long*)p)[i] : ((const int*)p)[i];
}
__device__ __forceinline__ int clampi(int v, int lo, int hi) {
    return v < lo ? lo : (v > hi ? hi : v);
}

// buffer selectors (device-side; no host symbol lookup needed)
__device__ __forceinline__ const float* node_buf(int sel, const float* xparam) {
    return sel == 0 ? xparam : (sel == 1 ? g_h1 : g_h2);   // 0=x, 1=h1, 2=h2
}
__device__ __forceinline__ float* hdst_buf(int sel) {
    return sel == 1 ? g_h1 : g_h2;
}
__device__ __forceinline__ const float* mlp_src(int sel) {
    switch (sel) { case 0: return g_pool; case 1: return g_t1;
                   case 2: return g_t2;  default: return g_t3; }
}
__device__ __forceinline__ float* mlp_dst(int sel, float* outparam) {
    switch (sel) { case 1: return g_t1; case 2: return g_t2;
                   case 3: return g_t3; default: return outparam; }
}

// ---------------- dtype detection (parallel): int64 layout => odd 32-bit words zero ----------------
__global__ void k_detect(const int* __restrict__ ei32) {
    __shared__ int s_ok;
    if (threadIdx.x == 0) s_ok = 1;
    __syncthreads();
    int k = threadIdx.x;   // 256 threads, one pair each from two regions
    int bad = (ei32[2 * k + 1] != 0) | (ei32[2 * (100000 + k) + 1] != 0);
    if (bad) s_ok = 0;
    __syncthreads();
    if (threadIdx.x == 0) g_idx64 = s_ok;
}

// ---------------- zero in-degree counters ----------------
__global__ void k_zero() {
    int i = blockIdx.x * blockDim.x + threadIdx.x;
    if (i < N_NODES) g_deg[i] = 0;
}

// ---------------- per-dst in-degree ----------------
__global__ void k_count(const void* __restrict__ ei) {
    int e = blockIdx.x * blockDim.x + threadIdx.x;
    if (e >= N_EDGES) return;
    int d = clampi(load_idx(ei, (long)N_EDGES + e), 0, N_NODES - 1);
    atomicAdd(&g_deg[d], 1);
}

// ---------------- multi-block scan, phase A: per-block degree sums ----------------
__global__ __launch_bounds__(256) void k_scanA() {
    __shared__ int s[256];
    int node = blockIdx.x * 256 + threadIdx.x;
    int d = (node < N_NODES) ? g_deg[node] : 0;
    s[threadIdx.x] = d; __syncthreads();
    #pragma unroll
    for (int off = 128; off > 0; off >>= 1) {
        if (threadIdx.x < off) s[threadIdx.x] += s[threadIdx.x + off];
        __syncthreads();
    }
    if (threadIdx.x == 0) g_bsum[blockIdx.x] = s[0];
}

// ---------------- phase B: scan block sums -> exclusive block offsets + total ----------------
__global__ __launch_bounds__(256) void k_scanB() {
    __shared__ int s[256];
    int t = threadIdx.x;
    int v = (t < SCAN_BLOCKS) ? g_bsum[t] : 0;
    s[t] = v; __syncthreads();
    #pragma unroll
    for (int off = 1; off < 256; off <<= 1) {
        int u = (t >= off) ? s[t - off] : 0;
        __syncthreads();
        s[t] += u;
        __syncthreads();
    }
    if (t < SCAN_BLOCKS) g_boff[t] = s[t] - v;         // exclusive
    if (t == 255) g_rowstart[N_NODES] = s[255];        // total edge count
}

// ---------------- phase C: per-block exclusive scan + offset -> rowstart, cursor ----------------
__global__ __launch_bounds__(256) void k_scanC() {
    __shared__ int s[256];
    int t = threadIdx.x;
    int node = blockIdx.x * 256 + t;
    int d = (node < N_NODES) ? g_deg[node] : 0;
    s[t] = d; __syncthreads();
    #pragma unroll
    for (int off = 1; off < 256; off <<= 1) {
        int u = (t >= off) ? s[t - off] : 0;
        __syncthreads();
        s[t] += u;
        __syncthreads();
    }
    if (node < N_NODES) {
        int r = g_boff[blockIdx.x] + s[t] - d;   // exclusive within block + block offset
        g_rowstart[node] = r;
        g_cursor[node]   = r;
    }
}

// ---------------- fill CSR src lists ----------------
__global__ void k_fill(const void* __restrict__ ei) {
    int e = blockIdx.x * blockDim.x + threadIdx.x;
    if (e >= N_EDGES) return;
    int s = clampi(load_idx(ei, e),                 0, N_NODES - 1);
    int d = clampi(load_idx(ei, (long)N_EDGES + e), 0, N_NODES - 1);
    int slot = atomicAdd(&g_cursor[d], 1);
    if (slot < N_EDGES) g_csr[slot] = s;
}

// ---------------- graph boundaries via binary search on sorted batch ----------------
__global__ void k_gbounds(const void* __restrict__ batch) {
    int g = blockIdx.x * blockDim.x + threadIdx.x;
    if (g > NUM_GRAPHS) return;
    if (g == NUM_GRAPHS) { g_gstart[g] = N_NODES; return; }
    int lo = 0, hi = N_NODES;
    while (lo < hi) {
        int mid = (lo + hi) >> 1;
        if (load_idx(batch, mid) < g) lo = mid + 1; else hi = mid;
    }
    g_gstart[g] = lo;
}

// ---------------- dual GEMM: g_yl = X@Wl, g_yr = X@Wr  (X:[N,K], W:[K,64]) ----------------
template<int K>
__global__ __launch_bounds__(128) void k_gemm_dual(
    const float* __restrict__ Xparam, int xsel,
    const float* __restrict__ Wl, const float* __restrict__ Wr)
{
    const float* __restrict__ X = node_buf(xsel, Xparam);

    __shared__ float Xs[32][65];
    __shared__ float Wls[64][64];
    __shared__ float Wrs[64][64];

    const int tid  = threadIdx.x;
    const int row0 = blockIdx.x * 32;
    const int rowg = tid >> 4;   // 0..7  (4 rows each)
    const int colg = tid & 15;   // 0..15 (4 cols each)

    float accl[4][4] = {{0.f}}, accr[4][4] = {{0.f}};

    #pragma unroll
    for (int c = 0; c < K / 64; c++) {
        #pragma unroll
        for (int i = 0; i < 4; i++) {
            int f  = tid + i * 128;
            int r  = f >> 4;
            int c4 = f & 15;
            float4 v = make_float4(0.f, 0.f, 0.f, 0.f);
            if (row0 + r < N_NODES)
                v = *(const float4*)(X + (size_t)(row0 + r) * K + c * 64 + c4 * 4);
            Xs[r][c4*4+0] = v.x; Xs[r][c4*4+1] = v.y;
            Xs[r][c4*4+2] = v.z; Xs[r][c4*4+3] = v.w;
        }
        #pragma unroll
        for (int i = 0; i < 8; i++) {
            int f  = tid + i * 128;
            int r  = f >> 4;
            int c4 = f & 15;
            ((float4*)Wls)[r*16 + c4] = *(const float4*)(Wl + (size_t)(c*64 + r) * 64 + c4 * 4);
            ((float4*)Wrs)[r*16 + c4] = *(const float4*)(Wr + (size_t)(c*64 + r) * 64 + c4 * 4);
        }
        __syncthreads();

        #pragma unroll 8
        for (int k = 0; k < 64; k++) {
            float4 wl = ((float4*)Wls)[k*16 + colg];
            float4 wr = ((float4*)Wrs)[k*16 + colg];
            #pragma unroll
            for (int i = 0; i < 4; i++) {
                float xv = Xs[rowg*4 + i][k];
                accl[i][0] += xv * wl.x; accl[i][1] += xv * wl.y;
                accl[i][2] += xv * wl.z; accl[i][3] += xv * wl.w;
                accr[i][0] += xv * wr.x; accr[i][1] += xv * wr.y;
                accr[i][2] += xv * wr.z; accr[i][3] += xv * wr.w;
            }
        }
        __syncthreads();
    }

    #pragma unroll
    for (int i = 0; i < 4; i++) {
        int r = row0 + rowg*4 + i;
        if (r < N_NODES) {
            *(float4*)(g_yl + (size_t)r * 64 + colg * 4) =
                make_float4(accl[i][0], accl[i][1], accl[i][2], accl[i][3]);
            *(float4*)(g_yr + (size_t)r * 64 + colg * 4) =
                make_float4(accr[i][0], accr[i][1], accr[i][2], accr[i][3]);
        }
    }
}

// ---------------- gather-aggregate + finish, fused ----------------
// h[v] = (sum_{u in N(v)} yl[u]) / max(deg,1) + bl + yr[v]
// 16 threads per node, each owning 4 columns (one float4).
__global__ void k_aggregate(const float* __restrict__ bl, int dstsel) {
    int tid = blockIdx.x * blockDim.x + threadIdx.x;
    if (tid >= N_NODES * 16) return;
    float* __restrict__ hout = hdst_buf(dstsel);
    const int v  = tid >> 4;
    const int c4 = (tid & 15) << 2;

    const int start = g_rowstart[v];
    const int end   = g_rowstart[v + 1];

    float4 acc = make_float4(0.f, 0.f, 0.f, 0.f);
    int i = start;
    for (; i + 4 <= end; i += 4) {
        int s0 = g_csr[i], s1 = g_csr[i+1], s2 = g_csr[i+2], s3 = g_csr[i+3];
        float4 a0 = *(const float4*)(g_yl + (size_t)s0 * 64 + c4);
        float4 a1 = *(const float4*)(g_yl + (size_t)s1 * 64 + c4);
        float4 a2 = *(const float4*)(g_yl + (size_t)s2 * 64 + c4);
        float4 a3 = *(const float4*)(g_yl + (size_t)s3 * 64 + c4);
        acc.x += a0.x + a1.x + a2.x + a3.x;
        acc.y += a0.y + a1.y + a2.y + a3.y;
        acc.z += a0.z + a1.z + a2.z + a3.z;
        acc.w += a0.w + a1.w + a2.w + a3.w;
    }
    for (; i < end; i++) {
        int s = g_csr[i];
        float4 a = *(const float4*)(g_yl + (size_t)s * 64 + c4);
        acc.x += a.x; acc.y += a.y; acc.z += a.z; acc.w += a.w;
    }

    float inv = 1.0f / fmaxf((float)(end - start), 1.0f);
    float4 r = *(const float4*)(g_yr + (size_t)v * 64 + c4);
    float4 b = *(const float4*)(bl + c4);
    float4 o = make_float4(acc.x * inv + b.x + r.x,
                           acc.y * inv + b.y + r.y,
                           acc.z * inv + b.z + r.z,
                           acc.w * inv + b.w + r.w);
    *(float4*)(hout + (size_t)v * 64 + c4) = o;
}

// ---------------- contiguous-segment pool (sums; mean folded into lin1) ----------------
__global__ __launch_bounds__(256) void k_pool(int srcsel) {
    const float* __restrict__ h = hdst_buf(srcsel);
    const int g = blockIdx.x;
    const int start = g_gstart[g], end = g_gstart[g + 1];
    const int col = threadIdx.x & 63;
    const int rg  = threadIdx.x >> 6;   // 0..3
    float acc = 0.f;
    for (int v = start + rg; v < end; v += 4)
        acc += h[(size_t)v * 64 + col];
    __shared__ float s[4][64];
    s[rg][col] = acc; __syncthreads();
    if (rg == 0)
        g_pool[(size_t)g * 64 + col] = s[0][col] + s[1][col] + s[2][col] + s[3][col];
}

// ---------------- small MLP GEMM: C[m] = (A[m] * scale) @ W + bias ----------------
__global__ void k_mlp_gemm(int asel, const float* __restrict__ W,
                           const float* __restrict__ bias, int csel,
                           float* outparam, int K, int Nc, int divide) {
    __shared__ float As[256];
    const float* __restrict__ A = mlp_src(asel);
    float* __restrict__ C = mlp_dst(csel, outparam);
    int m = blockIdx.x;
    float scale = 1.0f;
    if (divide) scale = 1.0f / fmaxf((float)(g_gstart[m + 1] - g_gstart[m]), 1.0f);
    for (int k = threadIdx.x; k < K; k += blockDim.x)
        As[k] = A[(size_t)m * K + k] * scale;
    __syncthreads();
    for (int n = threadIdx.x; n < Nc; n += blockDim.x) {
        float acc = bias[n];
        for (int k = 0; k < K; k++)
            acc += As[k] * W[(size_t)k * Nc + n];
        C[(size_t)m * Nc + n] = acc;
    }
}

// ---------------- batchnorm (training stats over 256 rows) + tanh, in place ----------------
__global__ void k_bn_tanh(int sel, const float* __restrict__ gm,
                          const float* __restrict__ bt, int Nc) {
    float* __restrict__ X = mlp_dst(sel, nullptr);
    int col = blockIdx.x;
    int t   = threadIdx.x;      // 256 threads = 256 rows
    __shared__ float red[256];
    float v = X[(size_t)t * Nc + col];
    red[t] = v; __syncthreads();
    for (int s = 128; s > 0; s >>= 1) { if (t < s) red[t] += red[t + s]; __syncthreads(); }
    float mean = red[0] * (1.0f / NUM_GRAPHS);
    __syncthreads();
    float d = v - mean;
    red[t] = d * d; __syncthreads();
    for (int s = 128; s > 0; s >>= 1) { if (t < s) red[t] += red[t + s]; __syncthreads(); }
    float var = red[0] * (1.0f / NUM_GRAPHS);
    X[(size_t)t * Nc + col] = tanhf(d * rsqrtf(var + BN_EPS) * gm[col] + bt[col]);
}

extern "C" void kernel_launch(void* const* d_in, const int* in_sizes, int n_in,
                              void* d_out, int out_size) {
    const float* x     = (const float*)d_in[0];
    const void*  ei    = d_in[1];
    const void*  batch = d_in[2];
    const float* W1l = (const float*)d_in[3];
    const float* b1l = (const float*)d_in[4];
    const float* W1r = (const float*)d_in[5];
    const float* W2l = (const float*)d_in[6];
    const float* b2l = (const float*)d_in[7];
    const float* W2r = (const float*)d_in[8];
    const float* W3l = (const float*)d_in[9];
    const float* b3l = (const float*)d_in[10];
    const float* W3r = (const float*)d_in[11];
    const float* lin1_w = (const float*)d_in[12];
    const float* lin1_b = (const float*)d_in[13];
    const float* g1  = (const float*)d_in[14];
    const float* be1 = (const float*)d_in[15];
    const float* lin2_w = (const float*)d_in[16];
    const float* lin2_b = (const float*)d_in[17];
    const float* g2  = (const float*)d_in[18];
    const float* be2 = (const float*)d_in[19];
    const float* lin3_w = (const float*)d_in[20];
    const float* lin3_b = (const float*)d_in[21];
    const float* g3  = (const float*)d_in[22];
    const float* be3 = (const float*)d_in[23];
    const float* lin4_w = (const float*)d_in[24];
    const float* lin4_b = (const float*)d_in[25];
    float* out = (float*)d_out;

    const int T = 256;
    const int gemm_grid   = (N_NODES + 31) / 32;
    const int edge_grid   = (N_EDGES + T - 1) / T;
    const int node16_grid = (N_NODES * 16 + T - 1) / T;

    // ---- detect index dtype, build CSR + graph bounds (shared across layers)
    k_detect <<<1, 256>>>((const int*)ei);
    k_zero   <<<(N_NODES + T - 1) / T, T>>>();
    k_count  <<<edge_grid, T>>>(ei);
    k_scanA  <<<SCAN_BLOCKS, 256>>>();
    k_scanB  <<<1, 256>>>();
    k_scanC  <<<SCAN_BLOCKS, 256>>>();
    k_fill   <<<edge_grid, T>>>(ei);
    k_gbounds<<<2, 256>>>(batch);

    // --- SAGE layer 1: x [N,128] -> h1 [N,64]
    k_gemm_dual<IN_DIM><<<gemm_grid, 128>>>(x, 0, W1l, W1r);
    k_aggregate<<<node16_grid, T>>>(b1l, 1);

    // --- SAGE layer 2: h1 -> h2
    k_gemm_dual<HDIM><<<gemm_grid, 128>>>(nullptr, 1, W2l, W2r);
    k_aggregate<<<node16_grid, T>>>(b2l, 2);

    // --- SAGE layer 3: h2 -> h1
    k_gemm_dual<HDIM><<<gemm_grid, 128>>>(nullptr, 2, W3l, W3r);
    k_aggregate<<<node16_grid, T>>>(b3l, 1);

    // --- global mean pool (sums; mean folded into lin1)
    k_pool<<<NUM_GRAPHS, 256>>>(1);

    // --- MLP head
    k_mlp_gemm<<<NUM_GRAPHS, 256>>>(0, lin1_w, lin1_b, 1, nullptr, HDIM,  HID,   1);
    k_bn_tanh <<<HID,        256>>>(1, g1, be1, HID);
    k_mlp_gemm<<<NUM_GRAPHS, 256>>>(1, lin2_w, lin2_b, 2, nullptr, HID,   HID/2, 0);
    k_bn_tanh <<<HID/2,      256>>>(2, g2, be2, HID/2);
    k_mlp_gemm<<<NUM_GRAPHS, 256>>>(2, lin3_w, lin3_b, 3, nullptr, HID/2, HID/4, 0);
    k_bn_tanh <<<HID/4,      256>>>(3, g3, be3, HID/4);
    k_mlp_gemm<<<NUM_GRAPHS, 256>>>(3, lin4_w, lin4_b, 0, out,     HID/4, 10,    0);
}